// round 2
// baseline (speedup 1.0000x reference)
#include <cuda_runtime.h>

#define BATCH 512
#define SEQ   512
#define VOCAB 1000
#define EMB   100
#define UNITS 64

typedef unsigned long long ull;

// Scratch: projected embedding table (emb @ Wxh + b), 1000 x 64 fp32 = 256 KB.
__device__ float g_embproj[VOCAB * UNITS];

// ---- packed f32x2 helpers (Blackwell 2xFP32 path, PTX-only) ----
__device__ __forceinline__ ull fma2(ull a, ull b, ull c) {
    ull d;
    asm("fma.rn.f32x2 %0, %1, %2, %3;" : "=l"(d) : "l"(a), "l"(b), "l"(c));
    return d;
}
__device__ __forceinline__ ull add2(ull a, ull b) {
    ull d;
    asm("add.rn.f32x2 %0, %1, %2;" : "=l"(d) : "l"(a), "l"(b));
    return d;
}
__device__ __forceinline__ ull pack2(float lo, float hi) {
    ull d;
    asm("mov.b64 %0, {%1, %2};"
        : "=l"(d) : "r"(__float_as_uint(lo)), "r"(__float_as_uint(hi)));
    return d;
}
__device__ __forceinline__ void unpack2(ull v, float& lo, float& hi) {
    unsigned a, b;
    asm("mov.b64 {%0, %1}, %2;" : "=r"(a), "=r"(b) : "l"(v));
    lo = __uint_as_float(a);
    hi = __uint_as_float(b);
}

// tanh(x) = 1 - 2/(exp(2x)+1). Saturates correctly at +/-1.
__device__ __forceinline__ float tanh_fast(float x) {
    float e = __expf(2.0f * x);
    return 1.0f - __fdividef(2.0f, e + 1.0f);
}

// ---------------------------------------------------------------------------
// Prologue: embproj[v][u] = sum_d emb[v][d] * Wxh[d][u] + b[u]
// ---------------------------------------------------------------------------
__global__ void k_embproj(const float* __restrict__ emb,
                          const float* __restrict__ Wxh,
                          const float* __restrict__ bias) {
    int v = blockIdx.x;        // vocab id
    int u = threadIdx.x;       // unit
    const float* er = emb + v * EMB;
    float a0 = bias[u], a1 = 0.f, a2 = 0.f, a3 = 0.f;
#pragma unroll
    for (int d = 0; d < EMB; d += 4) {
        a0 = fmaf(__ldg(er + d),     __ldg(Wxh + (d)     * UNITS + u), a0);
        a1 = fmaf(__ldg(er + d + 1), __ldg(Wxh + (d + 1) * UNITS + u), a1);
        a2 = fmaf(__ldg(er + d + 2), __ldg(Wxh + (d + 2) * UNITS + u), a2);
        a3 = fmaf(__ldg(er + d + 3), __ldg(Wxh + (d + 3) * UNITS + u), a3);
    }
    g_embproj[v * UNITS + u] = (a0 + a1) + (a2 + a3);
}

// ---------------------------------------------------------------------------
// Main: one warp per batch row. Lane l owns units u0=2l, u1=2l+1.
// k-pair packing: accumulators hold (sum over even k, sum over odd k); the
// FFMA2 multiplicand is the natural packed pair (h_k, h_{k+1}), so h lives in
// smem as 64 plain floats -> 8 LDS.128 per step, 1 STS.64 publish.
// ---------------------------------------------------------------------------
__global__ __launch_bounds__(128, 1)
void k_rnn(const int*   __restrict__ tokens,
           const float* __restrict__ Whh,
           const float* __restrict__ Wout,
           const float* __restrict__ bout,
           float*       __restrict__ out) {
    __shared__ __align__(16) float hs[4][UNITS];   // plain h per warp
    __shared__ int tok[4][SEQ];

    const int w    = threadIdx.x >> 5;
    const int lane = threadIdx.x & 31;
    const int row  = blockIdx.x * 4 + w;

    // Stage this row's tokens into smem (warp-local, coalesced int4).
    {
        const int4* src = (const int4*)(tokens + row * SEQ);
        int4* dst = (int4*)tok[w];
#pragma unroll
        for (int i = 0; i < 4; ++i)
            dst[lane + 32 * i] = src[lane + 32 * i];
    }

    // Weight registers, k-pair packed:
    //   wq0[j] = (W[2j][u0], W[2j+1][u0]),  wq1[j] = (W[2j][u1], W[2j+1][u1])
    ull wq0[UNITS / 2], wq1[UNITS / 2];
#pragma unroll
    for (int j = 0; j < UNITS / 2; ++j) {
        float2 we = *(const float2*)(Whh + (2 * j)     * UNITS + 2 * lane);
        float2 wo = *(const float2*)(Whh + (2 * j + 1) * UNITS + 2 * lane);
        wq0[j] = pack2(we.x, wo.x);
        wq1[j] = pack2(we.y, wo.y);
    }

    // h0 = 0
    *(float2*)(hs[w] + 2 * lane) = make_float2(0.f, 0.f);
    __syncwarp();

    const float* ep = g_embproj;
    float* hrow = hs[w];
    const ull* hp = (const ull*)hrow;   // packed (h_2j, h_2j+1) pairs

    // Preload xproj for t=0.
    float2 xt = *(const float2*)(ep + tok[w][0] * UNITS + 2 * lane);

    float h0v = 0.0f, h1v = 0.0f;

    for (int t = 0; t < SEQ; ++t) {
        // Prefetch next step's gathered xproj to hide L2 latency.
        int tn = tok[w][(t + 1 < SEQ) ? t + 1 : SEQ - 1];
        float2 xn = __ldg((const float2*)(ep + tn * UNITS + 2 * lane));

        // acc pairs: (sum over even k, sum over odd k). Seed with x_t.
        ull a0 = pack2(xt.x, 0.f), a1 = 0ull, a2 = 0ull, a3 = 0ull;  // unit u0
        ull b0 = pack2(xt.y, 0.f), b1 = 0ull, b2 = 0ull, b3 = 0ull;  // unit u1
#pragma unroll
        for (int j = 0; j < UNITS / 2; j += 4) {
            ulonglong2 p01 = *(const ulonglong2*)(hp + j);       // pairs j, j+1
            ulonglong2 p23 = *(const ulonglong2*)(hp + j + 2);   // pairs j+2, j+3
            a0 = fma2(p01.x, wq0[j],     a0);
            b0 = fma2(p01.x, wq1[j],     b0);
            a1 = fma2(p01.y, wq0[j + 1], a1);
            b1 = fma2(p01.y, wq1[j + 1], b1);
            a2 = fma2(p23.x, wq0[j + 2], a2);
            b2 = fma2(p23.x, wq1[j + 2], b2);
            a3 = fma2(p23.y, wq0[j + 3], a3);
            b3 = fma2(p23.y, wq1[j + 3], b3);
        }
        ull sa = add2(add2(a0, a1), add2(a2, a3));
        ull sb = add2(add2(b0, b1), add2(b2, b3));
        float sa0, sa1, sb0, sb1;
        unpack2(sa, sa0, sa1);
        unpack2(sb, sb0, sb1);
        h0v = tanh_fast(sa0 + sa1);
        h1v = tanh_fast(sb0 + sb1);

        // Publish h for next step: one STS.64, then warp-fence.
        *(float2*)(hrow + 2 * lane) = make_float2(h0v, h1v);
        __syncwarp();

        xt = xn;
    }

    // Epilogue: sigmoid(hT @ Wout + bout)
    float2 wo = *(const float2*)(Wout + 2 * lane);
    float part = h0v * wo.x + h1v * wo.y;
#pragma unroll
    for (int o = 16; o; o >>= 1)
        part += __shfl_xor_sync(0xffffffffu, part, o);
    if (lane == 0)
        out[row] = __fdividef(1.0f, 1.0f + __expf(-(part + bout[0])));
}

extern "C" void kernel_launch(void* const* d_in, const int* in_sizes, int n_in,
                              void* d_out, int out_size) {
    const int*   tokens = (const int*)d_in[0];
    const float* emb    = (const float*)d_in[1];
    const float* Wxh    = (const float*)d_in[2];
    const float* Whh    = (const float*)d_in[3];
    const float* b      = (const float*)d_in[4];
    const float* Wout   = (const float*)d_in[5];
    const float* bout   = (const float*)d_in[6];
    float* out = (float*)d_out;

    k_embproj<<<VOCAB, UNITS>>>(emb, Wxh, b);
    k_rnn<<<BATCH / 4, 128>>>(tokens, Whh, Wout, bout, out);
}

// round 3
// speedup vs baseline: 1.1270x; 1.1270x over previous
#include <cuda_runtime.h>

#define BATCH 512
#define SEQ   512
#define VOCAB 1000
#define EMB   100
#define UNITS 64

typedef unsigned long long ull;

// Scratch: projected embedding table (emb @ Wxh + b), 1000 x 64 fp32 = 256 KB.
__device__ float g_embproj[VOCAB * UNITS];

// ---- packed f32x2 helpers (Blackwell 2xFP32 path, PTX-only) ----
__device__ __forceinline__ ull fma2(ull a, ull b, ull c) {
    ull d;
    asm("fma.rn.f32x2 %0, %1, %2, %3;" : "=l"(d) : "l"(a), "l"(b), "l"(c));
    return d;
}
__device__ __forceinline__ ull add2(ull a, ull b) {
    ull d;
    asm("add.rn.f32x2 %0, %1, %2;" : "=l"(d) : "l"(a), "l"(b));
    return d;
}
__device__ __forceinline__ ull pack2(float lo, float hi) {
    ull d;
    asm("mov.b64 %0, {%1, %2};"
        : "=l"(d) : "r"(__float_as_uint(lo)), "r"(__float_as_uint(hi)));
    return d;
}
__device__ __forceinline__ void unpack2(ull v, float& lo, float& hi) {
    unsigned a, b;
    asm("mov.b64 {%0, %1}, %2;" : "=r"(a), "=r"(b) : "l"(v));
    lo = __uint_as_float(a);
    hi = __uint_as_float(b);
}

// tanh(x) = 1 - 2*rcp(exp2(2*log2e*x)+1). Saturates correctly at +/-1.
// Chain: FMUL(4) + EX2(16) + FADD(4) + RCP(16) + FFMA(4) ~= 44 cyc.
__device__ __forceinline__ float tanh_fast(float x) {
    float e, r;
    asm("ex2.approx.f32 %0, %1;" : "=f"(e) : "f"(x * 2.8853900817779268f));
    asm("rcp.approx.f32 %0, %1;" : "=f"(r) : "f"(e + 1.0f));
    return fmaf(-2.0f, r, 1.0f);
}

// ---------------------------------------------------------------------------
// Prologue: embproj[v][u] = sum_d emb[v][d] * Wxh[d][u] + b[u]
// ---------------------------------------------------------------------------
__global__ void k_embproj(const float* __restrict__ emb,
                          const float* __restrict__ Wxh,
                          const float* __restrict__ bias) {
    int v = blockIdx.x;        // vocab id
    int u = threadIdx.x;       // unit
    const float* er = emb + v * EMB;
    float a0 = bias[u], a1 = 0.f, a2 = 0.f, a3 = 0.f;
#pragma unroll
    for (int d = 0; d < EMB; d += 4) {
        a0 = fmaf(__ldg(er + d),     __ldg(Wxh + (d)     * UNITS + u), a0);
        a1 = fmaf(__ldg(er + d + 1), __ldg(Wxh + (d + 1) * UNITS + u), a1);
        a2 = fmaf(__ldg(er + d + 2), __ldg(Wxh + (d + 2) * UNITS + u), a2);
        a3 = fmaf(__ldg(er + d + 3), __ldg(Wxh + (d + 3) * UNITS + u), a3);
    }
    g_embproj[v * UNITS + u] = (a0 + a1) + (a2 + a3);
}

// ---------------------------------------------------------------------------
// Main: one warp per batch row. Lane l owns units u0=2l, u1=2l+1.
// k-pair packed FFMA2 matvec; h broadcast via smem (8 LDS.128/step).
// Gather of embproj prefetched TWO steps ahead so LDG L2 latency (~250cyc)
// is covered by two loop bodies.
// ---------------------------------------------------------------------------
__global__ __launch_bounds__(128, 1)
void k_rnn(const int*   __restrict__ tokens,
           const float* __restrict__ Whh,
           const float* __restrict__ Wout,
           const float* __restrict__ bout,
           float*       __restrict__ out) {
    __shared__ __align__(16) float hs[4][UNITS];   // plain h per warp
    __shared__ int tok[4][SEQ];

    const int w    = threadIdx.x >> 5;
    const int lane = threadIdx.x & 31;
    const int row  = blockIdx.x * 4 + w;

    // Stage this row's tokens into smem (warp-local, coalesced int4).
    {
        const int4* src = (const int4*)(tokens + row * SEQ);
        int4* dst = (int4*)tok[w];
#pragma unroll
        for (int i = 0; i < 4; ++i)
            dst[lane + 32 * i] = src[lane + 32 * i];
    }

    // Weight registers, k-pair packed:
    //   wq0[j] = (W[2j][u0], W[2j+1][u0]),  wq1[j] = (W[2j][u1], W[2j+1][u1])
    ull wq0[UNITS / 2], wq1[UNITS / 2];
#pragma unroll
    for (int j = 0; j < UNITS / 2; ++j) {
        float2 we = *(const float2*)(Whh + (2 * j)     * UNITS + 2 * lane);
        float2 wo = *(const float2*)(Whh + (2 * j + 1) * UNITS + 2 * lane);
        wq0[j] = pack2(we.x, wo.x);
        wq1[j] = pack2(we.y, wo.y);
    }

    // h0 = 0
    *(float2*)(hs[w] + 2 * lane) = make_float2(0.f, 0.f);
    __syncwarp();

    const float* ep = g_embproj;
    float* hrow = hs[w];
    const ull* hp = (const ull*)hrow;   // packed (h_2j, h_2j+1) pairs

    float h0v = 0.0f, h1v = 0.0f;

    // Double-buffered gather, prefetch distance 2.
    float2 xa = __ldg((const float2*)(ep + tok[w][0] * UNITS + 2 * lane));
    float2 xb = __ldg((const float2*)(ep + tok[w][1] * UNITS + 2 * lane));

    // One recurrence step on input xcur. 8 accumulators per unit: FFMA depth 4,
    // then 3-level add2 tree.
#define RNN_BODY(xcur)                                                        \
    {                                                                         \
        ull A[8], B[8];                                                       \
        A[0] = pack2((xcur).x, 0.f);                                          \
        B[0] = pack2((xcur).y, 0.f);                                          \
        _Pragma("unroll")                                                     \
        for (int i = 1; i < 8; ++i) { A[i] = 0ull; B[i] = 0ull; }             \
        _Pragma("unroll")                                                     \
        for (int g = 0; g < 4; ++g) {                                         \
            ulonglong2 q0 = *(const ulonglong2*)(hp + 8 * g);                 \
            ulonglong2 q1 = *(const ulonglong2*)(hp + 8 * g + 2);             \
            ulonglong2 q2 = *(const ulonglong2*)(hp + 8 * g + 4);             \
            ulonglong2 q3 = *(const ulonglong2*)(hp + 8 * g + 6);             \
            A[0] = fma2(q0.x, wq0[8 * g + 0], A[0]);                          \
            B[0] = fma2(q0.x, wq1[8 * g + 0], B[0]);                          \
            A[1] = fma2(q0.y, wq0[8 * g + 1], A[1]);                          \
            B[1] = fma2(q0.y, wq1[8 * g + 1], B[1]);                          \
            A[2] = fma2(q1.x, wq0[8 * g + 2], A[2]);                          \
            B[2] = fma2(q1.x, wq1[8 * g + 2], B[2]);                          \
            A[3] = fma2(q1.y, wq0[8 * g + 3], A[3]);                          \
            B[3] = fma2(q1.y, wq1[8 * g + 3], B[3]);                          \
            A[4] = fma2(q2.x, wq0[8 * g + 4], A[4]);                          \
            B[4] = fma2(q2.x, wq1[8 * g + 4], B[4]);                          \
            A[5] = fma2(q2.y, wq0[8 * g + 5], A[5]);                          \
            B[5] = fma2(q2.y, wq1[8 * g + 5], B[5]);                          \
            A[6] = fma2(q3.x, wq0[8 * g + 6], A[6]);                          \
            B[6] = fma2(q3.x, wq1[8 * g + 6], B[6]);                          \
            A[7] = fma2(q3.y, wq0[8 * g + 7], A[7]);                          \
            B[7] = fma2(q3.y, wq1[8 * g + 7], B[7]);                          \
        }                                                                     \
        ull sa = add2(add2(add2(A[0], A[1]), add2(A[2], A[3])),               \
                      add2(add2(A[4], A[5]), add2(A[6], A[7])));              \
        ull sb = add2(add2(add2(B[0], B[1]), add2(B[2], B[3])),               \
                      add2(add2(B[4], B[5]), add2(B[6], B[7])));              \
        float sa0, sa1, sb0, sb1;                                             \
        unpack2(sa, sa0, sa1);                                                \
        unpack2(sb, sb0, sb1);                                                \
        h0v = tanh_fast(sa0 + sa1);                                           \
        h1v = tanh_fast(sb0 + sb1);                                           \
        *(float2*)(hrow + 2 * lane) = make_float2(h0v, h1v);                  \
        __syncwarp();                                                         \
    }

    for (int t = 0; t < SEQ; t += 2) {
        // Prefetch t+2 and t+3 (clamped); consumed two bodies later.
        int i2 = (t + 2 < SEQ) ? t + 2 : SEQ - 1;
        int i3 = (t + 3 < SEQ) ? t + 3 : SEQ - 1;
        float2 xn0 = __ldg((const float2*)(ep + tok[w][i2] * UNITS + 2 * lane));
        float2 xn1 = __ldg((const float2*)(ep + tok[w][i3] * UNITS + 2 * lane));

        RNN_BODY(xa);
        RNN_BODY(xb);

        xa = xn0;
        xb = xn1;
    }
#undef RNN_BODY

    // Epilogue: sigmoid(hT @ Wout + bout)
    float2 wo = *(const float2*)(Wout + 2 * lane);
    float part = h0v * wo.x + h1v * wo.y;
#pragma unroll
    for (int o = 16; o; o >>= 1)
        part += __shfl_xor_sync(0xffffffffu, part, o);
    if (lane == 0) {
        float z = part + bout[0];
        float e, r;
        asm("ex2.approx.f32 %0, %1;" : "=f"(e) : "f"(-z * 1.4426950408889634f));
        asm("rcp.approx.f32 %0, %1;" : "=f"(r) : "f"(1.0f + e));
        out[row] = r;
    }
}

extern "C" void kernel_launch(void* const* d_in, const int* in_sizes, int n_in,
                              void* d_out, int out_size) {
    const int*   tokens = (const int*)d_in[0];
    const float* emb    = (const float*)d_in[1];
    const float* Wxh    = (const float*)d_in[2];
    const float* Whh    = (const float*)d_in[3];
    const float* b      = (const float*)d_in[4];
    const float* Wout   = (const float*)d_in[5];
    const float* bout   = (const float*)d_in[6];
    float* out = (float*)d_out;

    k_embproj<<<VOCAB, UNITS>>>(emb, Wxh, b);
    k_rnn<<<BATCH / 4, 128>>>(tokens, Whh, Wout, bout, out);
}